// round 1
// baseline (speedup 1.0000x reference)
#include <cuda_runtime.h>
#include <stdint.h>

#define N 2048
#define MAXC 128            // padded per-column CSC capacity (col nnz ~17 mean, <<128)

// ---- device scratch (no runtime allocation allowed) ----
__device__ int   g_row_nnz[N];
__device__ int   g_rowptr[N + 1];
__device__ int   g_col_cnt[N];
__device__ int   g_csc[N * MAXC];      // packed (t << 16) | u
__device__ float g_xT[4 * N * 32];     // xT[i*32 + b], i in [0, 8192)
__device__ float g_outT[4 * N * 32];   // outT[j*32 + b], j in [0, 8192)

// K0: transpose inputs (32 x 8192) -> xT (8192 x 32); block 0 also zeros col_cnt.
__global__ void k_prep(const float* __restrict__ inputs) {
    __shared__ float sh[32][33];
    int i0 = blockIdx.x * 32;
    int tx = threadIdx.x, ty = threadIdx.y;
    // read: inputs[b=ty][i0+tx], coalesced over tx
    sh[ty][tx] = inputs[ty * 8192 + i0 + tx];
    if (blockIdx.x == 0) {
        int tid = ty * 32 + tx;
        g_col_cnt[tid] = 0;
        g_col_cnt[tid + 1024] = 0;
    }
    __syncthreads();
    // write: xT[(i0+ty)*32 + tx], coalesced over tx (=b)
    g_xT[(i0 + ty) * 32 + tx] = sh[tx][ty];
}

// K1: one block per adjacency row u. Finds nonzeros, ranks them (t), scatters
// packed (t,u) into per-column CSC slots. Dominant kernel: reads 16MB.
__global__ void k_rows(const float* __restrict__ A) {
    int u = blockIdx.x;
    int tid = threadIdx.x;              // 256 threads, 8 elements each
    const float4* row = (const float4*)(A + (size_t)u * N);

    int myv[8];
    int cnt = 0;
#pragma unroll
    for (int q = 0; q < 2; q++) {
        float4 f = row[tid * 2 + q];
        int basev = (tid * 2 + q) * 4;
        if (f.x != 0.0f) myv[cnt++] = basev + 0;
        if (f.y != 0.0f) myv[cnt++] = basev + 1;
        if (f.z != 0.0f) myv[cnt++] = basev + 2;
        if (f.w != 0.0f) myv[cnt++] = basev + 3;
    }

    // block exclusive scan of cnt (256 threads = 8 warps)
    __shared__ int warp_sums[8];
    int lane = tid & 31, wid = tid >> 5;
    int inc = cnt;
#pragma unroll
    for (int off = 1; off < 32; off <<= 1) {
        int y = __shfl_up_sync(0xffffffffu, inc, off);
        if (lane >= off) inc += y;
    }
    if (lane == 31) warp_sums[wid] = inc;
    __syncthreads();
    if (wid == 0) {
        int w = (lane < 8) ? warp_sums[lane] : 0;
#pragma unroll
        for (int off = 1; off < 8; off <<= 1) {
            int y = __shfl_up_sync(0xffffffffu, w, off);
            if (lane >= off) w += y;
        }
        if (lane < 8) warp_sums[lane] = w;
    }
    __syncthreads();
    int excl = inc - cnt + ((wid > 0) ? warp_sums[wid - 1] : 0);

    for (int e = 0; e < cnt; e++) {
        int v = myv[e];
        int t = excl + e;               // row-rank of v within row u
        int slot = atomicAdd(&g_col_cnt[v], 1);
        if (slot < MAXC) g_csc[v * MAXC + slot] = (t << 16) | u;
    }
    if (tid == 0) g_row_nnz[u] = warp_sums[7];
}

// K2: exclusive prefix sum of row_nnz -> rowptr. Single block, 1024 threads.
__global__ void k_scan() {
    int tid = threadIdx.x;
    int a0 = g_row_nnz[2 * tid];
    int a1 = g_row_nnz[2 * tid + 1];
    int s = a0 + a1;
    int lane = tid & 31, wid = tid >> 5;
    __shared__ int wsum[32];
    int inc = s;
#pragma unroll
    for (int off = 1; off < 32; off <<= 1) {
        int y = __shfl_up_sync(0xffffffffu, inc, off);
        if (lane >= off) inc += y;
    }
    if (lane == 31) wsum[wid] = inc;
    __syncthreads();
    if (wid == 0) {
        int w = wsum[lane];
#pragma unroll
        for (int off = 1; off < 32; off <<= 1) {
            int y = __shfl_up_sync(0xffffffffu, w, off);
            if (lane >= off) w += y;
        }
        wsum[lane] = w;
    }
    __syncthreads();
    int excl = inc - s + ((wid > 0) ? wsum[wid - 1] : 0);
    g_rowptr[2 * tid] = excl;
    g_rowptr[2 * tid + 1] = excl + a0;
    if (tid == 1023) g_rowptr[N] = excl + s;
}

// K3: one block per output column v (node). 128 threads = 4 warps (c) x 32 lanes (b).
// Gather over incoming edges (u,t); no output atomics; bias folded in.
__global__ void k_cols(const float* __restrict__ ker,
                       const float* __restrict__ bias,
                       int nnz4 /* = 4*NNZ, from in_sizes */) {
    int v = blockIdx.x;
    int tid = threadIdx.x;
    int c = tid >> 5, b = tid & 31;

    __shared__ int tmp_u[MAXC], tmp_t[MAXC];
    __shared__ int s_u[MAXC], s_base[MAXC], s_rn[MAXC];

    int cnt = g_col_cnt[v];
    if (cnt > MAXC) cnt = MAXC;

    if (tid < cnt) {
        int p = g_csc[v * MAXC + tid];
        tmp_u[tid] = p & 0xffff;
        tmp_t[tid] = p >> 16;
    }
    __syncthreads();
    // deterministic order: rank-sort by u (u unique per column), O(cnt^2) tiny
    if (tid < cnt) {
        int myu = tmp_u[tid];
        int r = 0;
        for (int e = 0; e < cnt; e++) r += (tmp_u[e] < myu);
        s_u[r] = myu;
        s_base[r] = 4 * g_rowptr[myu] + tmp_t[tid];
        s_rn[r] = g_row_nnz[myu];
    }
    __syncthreads();

    float acc = 0.0f;
    for (int e = 0; e < cnt; e++) {
        int u = s_u[e];
        int base = s_base[e] + c * s_rn[e];
        const float* xr = &g_xT[(size_t)u * 32 + b];
#pragma unroll
        for (int ic = 0; ic < 4; ic++) {
            float w = __ldg(&ker[ic * nnz4 + base]);   // warp-uniform broadcast
            acc += xr[ic * (N * 32)] * w;              // coalesced over b
        }
    }
    int j = c * N + v;
    g_outT[(size_t)j * 32 + b] = acc + __ldg(&bias[j]);
}

// K4: transpose outT (8192 x 32) -> out (32 x 8192), fully coalesced.
__global__ void k_outT(float* __restrict__ out) {
    __shared__ float sh[32][33];
    int j0 = blockIdx.x * 32;
    int tx = threadIdx.x, ty = threadIdx.y;
    sh[ty][tx] = g_outT[(j0 + ty) * 32 + tx];   // coalesced over tx (=b)
    __syncthreads();
    out[ty * 8192 + j0 + tx] = sh[tx][ty];      // coalesced over tx (=j)
}

extern "C" void kernel_launch(void* const* d_in, const int* in_sizes, int n_in,
                              void* d_out, int out_size) {
    const float* inputs = (const float*)d_in[0];  // (32, 8192)
    const float* A      = (const float*)d_in[1];  // (2048, 2048)
    const float* ker    = (const float*)d_in[2];  // (16*NNZ,)
    const float* bias   = (const float*)d_in[3];  // (8192,)
    float* out = (float*)d_out;

    int nnz4 = in_sizes[2] / 4;   // kernel len = channels*in_chan*NNZ = 16*NNZ

    dim3 t32x32(32, 32);
    k_prep<<<256, t32x32>>>(inputs);
    k_rows<<<N, 256>>>(A);
    k_scan<<<1, 1024>>>();
    k_cols<<<N, 128>>>(ker, bias, nnz4);
    k_outT<<<256, t32x32>>>(out);
}